// round 9
// baseline (speedup 1.0000x reference)
#include <cuda_runtime.h>
#include <cuda_bf16.h>

#define N_COLS 4096
#define NT     1024         // threads per row-CTA; 4 elements/thread/array

__device__ float g_row_sums[8192];

// float -> FMNMX (fma pipe), int -> IMNMX (alu pipe).
// Inputs are non-negative floats, so int bit-pattern order == float order.
static __device__ __forceinline__ float mn(float x, float y) { return fminf(x, y); }
static __device__ __forceinline__ float mx(float x, float y) { return fmaxf(x, y); }
static __device__ __forceinline__ int   mn(int x, int y)     { return ::min(x, y); }
static __device__ __forceinline__ int   mx(int x, int y)     { return ::max(x, y); }

template <typename T>
static __device__ __forceinline__ void ce(T& x, T& y, bool up) {
    T lo = mn(x, y);
    T hi = mx(x, y);
    x = up ? lo : hi;
    y = up ? hi : lo;
}
template <typename T>
static __device__ __forceinline__ void cea(T& x, T& y) {
    T lo = mn(x, y);
    y = mx(x, y);
    x = lo;
}

// Bitonic k=2,4 on 4 register elements (global idx 4t+e).
template <typename T>
static __device__ __forceinline__ void sort4(T r[4], bool up4) {
    ce(r[0], r[1], true ); ce(r[2], r[3], false);       // k=2
    ce(r[0], r[2], up4);   ce(r[1], r[3], up4);         // k=4, j=2
    ce(r[0], r[1], up4);   ce(r[2], r[3], up4);         // k=4, j=1
}

template <typename T>
static __device__ __forceinline__ void local_merge4(T r[4], bool up) {
    ce(r[0], r[2], up); ce(r[1], r[3], up);
    ce(r[0], r[1], up); ce(r[2], r[3], up);
}

// One cross-thread stage on both arrays (interleaved for ILP).
static __device__ __forceinline__ void shfl_stage2(float a[4], int b[4],
                                                   int m, bool keep_min) {
    #pragma unroll
    for (int e = 0; e < 4; e++) {
        float oa = __shfl_xor_sync(0xffffffffu, a[e], m);
        int   ob = __shfl_xor_sync(0xffffffffu, b[e], m);
        a[e] = keep_min ? mn(a[e], oa) : mx(a[e], oa);
        b[e] = keep_min ? mn(b[e], ob) : mx(b[e], ob);
    }
}

__global__ __launch_bounds__(NT, 2)
void w1_row_kernel(const float4* __restrict__ pred,
                   const float4* __restrict__ tru)
{
    // +8 padding so merge windows can read past the pair end unpredicated.
    __shared__ __align__(16) float sa[N_COLS + 8];
    __shared__ __align__(16) int   sb[N_COLS + 8];
    __shared__ float red[32];

    const int row = blockIdx.x;
    const int t   = threadIdx.x;

    float a[4]; int b[4];
    {
        const size_t base = (size_t)row * (N_COLS / 4) + t;
        float4 p = pred[base];
        float4 q = tru[base];
        a[0]=p.x; a[1]=p.y; a[2]=p.z; a[3]=p.w;
        b[0]=__float_as_int(q.x); b[1]=__float_as_int(q.y);
        b[2]=__float_as_int(q.z); b[3]=__float_as_int(q.w);
    }

    // ---- Phase 1: bitonic to ascending runs of 512 ----
    const bool up4 = ((t & 1) == 0);
    sort4(a, up4);
    sort4(b, up4);

    // k = 8..128: all cross-thread strides within a warp (j=4..64 -> m=1..16)
    #pragma unroll
    for (int k = 8; k <= 128; k <<= 1) {
        const bool up = (((t << 2) & k) == 0);
        #pragma unroll
        for (int j = k >> 1; j >= 4; j >>= 1) {
            const int  m        = j >> 2;
            const bool keep_min = (((t & m) == 0) == up);
            shfl_stage2(a, b, m, keep_min);
        }
        local_merge4(a, up);
        local_merge4(b, up);
    }

    // k = 256: j=128 -> smem exchange (partner t^32), then shfl, then local
    {
        const bool up = ((t & 64) == 0);   // ((4t & 256)==0)
        #pragma unroll
        for (int e = 0; e < 4; e++) { sa[e * NT + t] = a[e]; sb[e * NT + t] = b[e]; }
        __syncthreads();
        {
            const int  pt = t ^ 32;
            const bool km = (((t & 32) == 0) == up);
            #pragma unroll
            for (int e = 0; e < 4; e++) {
                float oa = sa[e * NT + pt];
                int   ob = sb[e * NT + pt];
                a[e] = km ? mn(a[e], oa) : mx(a[e], oa);
                b[e] = km ? mn(b[e], ob) : mx(b[e], ob);
            }
        }
        __syncthreads();
        #pragma unroll
        for (int m = 16; m >= 1; m >>= 1) {
            const bool keep_min = (((t & m) == 0) == up);
            shfl_stage2(a, b, m, keep_min);
        }
        local_merge4(a, up);
        local_merge4(b, up);
    }

    // k = 512, forced ascending: j=256 (t^64) and j=128 (t^32) via smem
    {
        #pragma unroll
        for (int e = 0; e < 4; e++) { sa[e * NT + t] = a[e]; sb[e * NT + t] = b[e]; }
        __syncthreads();
        {
            const int  pt = t ^ 64;
            const bool km = ((t & 64) == 0);
            #pragma unroll
            for (int e = 0; e < 4; e++) {
                float oa = sa[e * NT + pt];
                int   ob = sb[e * NT + pt];
                a[e] = km ? mn(a[e], oa) : mx(a[e], oa);
                b[e] = km ? mn(b[e], ob) : mx(b[e], ob);
            }
        }
        __syncthreads();
        #pragma unroll
        for (int e = 0; e < 4; e++) { sa[e * NT + t] = a[e]; sb[e * NT + t] = b[e]; }
        __syncthreads();
        {
            const int  pt = t ^ 32;
            const bool km = ((t & 32) == 0);
            #pragma unroll
            for (int e = 0; e < 4; e++) {
                float oa = sa[e * NT + pt];
                int   ob = sb[e * NT + pt];
                a[e] = km ? mn(a[e], oa) : mx(a[e], oa);
                b[e] = km ? mn(b[e], ob) : mx(b[e], ob);
            }
        }
        __syncthreads();
        #pragma unroll
        for (int m = 16; m >= 1; m >>= 1) {
            const bool keep_min = ((t & m) == 0);
            shfl_stage2(a, b, m, keep_min);
        }
        local_merge4(a, true);
        local_merge4(b, true);
    }

    // canonical layout: thread t owns [t*4, t*4+4)
    reinterpret_cast<float4*>(sa)[t] = make_float4(a[0], a[1], a[2], a[3]);
    reinterpret_cast<int4*>(sb)[t]   = make_int4(b[0], b[1], b[2], b[3]);
    __syncthreads();

    // ---- Phase 2: 3 merge-path passes 512 -> 4096, fused dual search ----
    const float INFF = __int_as_float(0x7f800000);
    const int   INFI = 0x7f800000;

    float of[4]; int oi[4];
    #pragma unroll
    for (int p = 0; p < 3; p++) {
        const int L     = 512 << p;
        const int d0    = t * 4;
        const int base2 = d0 & ~(2 * L - 1);
        const int d     = d0 - base2;

        const float* __restrict__ Af = sa + base2;
        const float* __restrict__ Bf = Af + L;
        const int*   __restrict__ Ai = sb + base2;
        const int*   __restrict__ Bi = Ai + L;

        // dual binary search (interleaved for ILP on the dependent LDS chains)
        int lof = (d > L) ? (d - L) : 0;
        int hif = (d < L) ? d : L;
        int loi = lof, hii = hif;
        while ((lof < hif) | (loi < hii)) {
            if (lof < hif) {
                int m = (lof + hif) >> 1;
                if (Af[m] < Bf[d - 1 - m]) lof = m + 1; else hif = m;
            }
            if (loi < hii) {
                int m = (loi + hii) >> 1;
                if (Ai[m] < Bi[d - 1 - m]) loi = m + 1; else hii = m;
            }
        }

        // float array: window + lowest-4 + ascending sort of bitonic quartet
        {
            const int i = lof, j = d - lof;
            float Aw[4], Bw[4];
            #pragma unroll
            for (int r = 0; r < 4; r++) Aw[r] = (i + r < L) ? Af[i + r] : INFF;
            #pragma unroll
            for (int r = 0; r < 4; r++) Bw[r] = (j + r < L) ? Bf[j + r] : INFF;
            #pragma unroll
            for (int r = 0; r < 4; r++) of[r] = mn(Aw[r], Bw[3 - r]);
            cea(of[0], of[2]); cea(of[1], of[3]);
            cea(of[0], of[1]); cea(of[2], of[3]);
        }
        // int array
        {
            const int i = loi, j = d - loi;
            int Aw[4], Bw[4];
            #pragma unroll
            for (int r = 0; r < 4; r++) Aw[r] = (i + r < L) ? Ai[i + r] : INFI;
            #pragma unroll
            for (int r = 0; r < 4; r++) Bw[r] = (j + r < L) ? Bi[j + r] : INFI;
            #pragma unroll
            for (int r = 0; r < 4; r++) oi[r] = mn(Aw[r], Bw[3 - r]);
            cea(oi[0], oi[2]); cea(oi[1], oi[3]);
            cea(oi[0], oi[1]); cea(oi[2], oi[3]);
        }
        __syncthreads();

        if (p < 2) {
            reinterpret_cast<float4*>(sa)[t] = make_float4(of[0], of[1], of[2], of[3]);
            reinterpret_cast<int4*>(sb)[t]   = make_int4(oi[0], oi[1], oi[2], oi[3]);
            __syncthreads();
        }
    }

    // ---- |sorted diff| reduction; final quartets in registers ----
    float local = 0.0f;
    #pragma unroll
    for (int r = 0; r < 4; r++)
        local += fabsf(of[r] - __int_as_float(oi[r]));

    #pragma unroll
    for (int o = 16; o > 0; o >>= 1)
        local += __shfl_down_sync(0xffffffffu, local, o);
    if ((t & 31) == 0) red[t >> 5] = local;
    __syncthreads();
    if (t < 32) {
        float v = red[t];
        #pragma unroll
        for (int o = 16; o > 0; o >>= 1)
            v += __shfl_down_sync(0xffffffffu, v, o);
        if (t == 0) g_row_sums[row] = v;
    }
}

// Deterministic final reduction: single block, fixed iteration order.
__global__ void w1_reduce_kernel(float* __restrict__ out, int B)
{
    __shared__ float red[32];
    float local = 0.0f;
    for (int i = threadIdx.x; i < B; i += 1024)
        local += g_row_sums[i];
    #pragma unroll
    for (int o = 16; o > 0; o >>= 1)
        local += __shfl_down_sync(0xffffffffu, local, o);
    if ((threadIdx.x & 31) == 0) red[threadIdx.x >> 5] = local;
    __syncthreads();
    if (threadIdx.x < 32) {
        float v = red[threadIdx.x];
        #pragma unroll
        for (int o = 16; o > 0; o >>= 1)
            v += __shfl_down_sync(0xffffffffu, v, o);
        if (threadIdx.x == 0)
            out[0] = v / ((float)N_COLS * (float)B);
    }
}

extern "C" void kernel_launch(void* const* d_in, const int* in_sizes, int n_in,
                              void* d_out, int out_size)
{
    const float4* pred = (const float4*)d_in[0];
    const float4* tru  = (const float4*)d_in[1];
    float* out = (float*)d_out;

    const int B = in_sizes[0] / N_COLS;  // 4096

    w1_row_kernel<<<B, NT>>>(pred, tru);
    w1_reduce_kernel<<<1, 1024>>>(out, B);
}

// round 11
// speedup vs baseline: 1.6415x; 1.6415x over previous
#include <cuda_runtime.h>
#include <cuda_bf16.h>

#define N_COLS 4096
#define NT     512
#define M_BKT  2048
#define BPT    (M_BKT / NT)        // 4 buckets owned per thread
#define BKT_W  (1.0f / (float)M_BKT)

__device__ float g_row_sums[8192];

static __device__ __forceinline__ int bkt(float x) {
    int b = (int)(x * (float)M_BKT);
    return (b > M_BKT - 1) ? (M_BKT - 1) : ((b < 0) ? 0 : b);
}

__global__ __launch_bounds__(NT, 3)
void w1_row_kernel(const float4* __restrict__ pred,
                   const float4* __restrict__ tru)
{
    // counts (packed u|v<<16) -> combined offsets -> scatter cursors
    __shared__ unsigned int cursor[M_BKT];          // 8 KB
    __shared__ unsigned int slab[2 * N_COLS];       // 32 KB: bucketed keys
    __shared__ unsigned int wsum[16];
    __shared__ float red[16];

    const int row  = blockIdx.x;
    const int t    = threadIdx.x;
    const int lane = t & 31;
    const int wid  = t >> 5;

    // zero own counters
    #pragma unroll
    for (int j = 0; j < BPT; j++) cursor[t * BPT + j] = 0u;

    const size_t rbase = (size_t)row * (N_COLS / 4);
    float4 p0 = pred[rbase + t];
    float4 p1 = pred[rbase + t + NT];
    float4 q0 = tru[rbase + t];
    float4 q1 = tru[rbase + t + NT];
    __syncthreads();   // counters zeroed before atomics

    // ---- histogram: u -> +1 (low half), v -> +1<<16 (high half) ----
    {
        float up[8] = {p0.x, p0.y, p0.z, p0.w, p1.x, p1.y, p1.z, p1.w};
        float vp[8] = {q0.x, q0.y, q0.z, q0.w, q1.x, q1.y, q1.z, q1.w};
        #pragma unroll
        for (int e = 0; e < 8; e++) atomicAdd(&cursor[bkt(up[e])], 1u);
        #pragma unroll
        for (int e = 0; e < 8; e++) atomicAdd(&cursor[bkt(vp[e])], 0x10000u);
    }
    __syncthreads();

    // ---- packed exclusive scan over M_BKT buckets (thread owns BPT contiguous) ----
    unsigned int eP[BPT];     // packed exclusive prefix within thread
    unsigned int oB[BPT];     // combined slab offset per owned bucket
    int          c0[BPT];     // cumU - cumV entering the bucket
    {
        unsigned int run = 0;
        unsigned int h[BPT];
        #pragma unroll
        for (int j = 0; j < BPT; j++) {
            h[j]  = cursor[t * BPT + j];
            eP[j] = run;
            run  += h[j];
        }
        // warp inclusive scan of run
        unsigned int inc = run;
        #pragma unroll
        for (int o = 1; o < 32; o <<= 1) {
            unsigned int n2 = __shfl_up_sync(0xffffffffu, inc, o);
            if (lane >= o) inc += n2;
        }
        unsigned int wexc = inc - run;
        if (lane == 31) wsum[wid] = inc;
        __syncthreads();
        if (t < 32) {
            unsigned int v2 = (t < 16) ? wsum[t] : 0u;
            unsigned int i2 = v2;
            #pragma unroll
            for (int o = 1; o < 32; o <<= 1) {
                unsigned int n2 = __shfl_up_sync(0xffffffffu, i2, o);
                if (t >= o) i2 += n2;
            }
            if (t < 16) wsum[t] = i2 - v2;   // exclusive warp base
        }
        __syncthreads();
        const unsigned int base = wsum[wid] + wexc;
        #pragma unroll
        for (int j = 0; j < BPT; j++) {
            unsigned int P = base + eP[j];               // packed cumU | cumV<<16
            unsigned int cu = P & 0xFFFFu, cv = P >> 16;
            oB[j] = cu + cv;
            c0[j] = (int)cu - (int)cv;
            cursor[t * BPT + j] = oB[j];                 // own bucket: safe rewrite
        }
    }
    __syncthreads();

    // ---- scatter keys: key = (bits & ~1) | tag  (tag: u=0, v=1) ----
    {
        float up[8] = {p0.x, p0.y, p0.z, p0.w, p1.x, p1.y, p1.z, p1.w};
        float vp[8] = {q0.x, q0.y, q0.z, q0.w, q1.x, q1.y, q1.z, q1.w};
        #pragma unroll
        for (int e = 0; e < 8; e++) {
            unsigned int pos = atomicAdd(&cursor[bkt(up[e])], 1u);
            slab[pos] = __float_as_uint(up[e]) & ~1u;
        }
        #pragma unroll
        for (int e = 0; e < 8; e++) {
            unsigned int pos = atomicAdd(&cursor[bkt(vp[e])], 1u);
            slab[pos] = (__float_as_uint(vp[e]) & ~1u) | 1u;
        }
    }
    __syncthreads();

    // ---- per-bucket: insertion sort + |counter| walk ----
    float acc = 0.0f;
    #pragma unroll
    for (int j = 0; j < BPT; j++) {
        const int m   = t * BPT + j;
        const unsigned int o = oB[j];
        const int cnt = (int)(cursor[m] - o);

        // insertion sort slab[o .. o+cnt)
        for (int i2 = 1; i2 < cnt; i2++) {
            unsigned int key = slab[o + i2];
            int j2 = i2 - 1;
            while (j2 >= 0 && slab[o + j2] > key) {
                slab[o + j2 + 1] = slab[o + j2];
                j2--;
            }
            slab[o + j2 + 1] = key;
        }

        const float L = (float)m * BKT_W;
        float xp = L;
        int   c  = c0[j];
        for (int s = 0; s < cnt; s++) {
            unsigned int k2 = slab[o + s];
            float x = __uint_as_float(k2 & ~1u);
            acc += fabsf((float)c) * (x - xp);
            c += (k2 & 1u) ? -1 : 1;
            xp = x;
        }
        acc += fabsf((float)c) * (L + BKT_W - xp);
    }

    // ---- block reduction -> g_row_sums[row] ----
    #pragma unroll
    for (int o = 16; o > 0; o >>= 1)
        acc += __shfl_down_sync(0xffffffffu, acc, o);
    if (lane == 0) red[wid] = acc;
    __syncthreads();
    if (t < 32) {
        float v = (t < 16) ? red[t] : 0.0f;
        #pragma unroll
        for (int o = 8; o > 0; o >>= 1)
            v += __shfl_down_sync(0xffffffffu, v, o);
        if (t == 0) g_row_sums[row] = v;
    }
}

// Deterministic final reduction: single block, fixed iteration order.
__global__ void w1_reduce_kernel(float* __restrict__ out, int B)
{
    __shared__ float red[32];
    float local = 0.0f;
    for (int i = threadIdx.x; i < B; i += 1024)
        local += g_row_sums[i];
    #pragma unroll
    for (int o = 16; o > 0; o >>= 1)
        local += __shfl_down_sync(0xffffffffu, local, o);
    if ((threadIdx.x & 31) == 0) red[threadIdx.x >> 5] = local;
    __syncthreads();
    if (threadIdx.x < 32) {
        float v = red[threadIdx.x];
        #pragma unroll
        for (int o = 16; o > 0; o >>= 1)
            v += __shfl_down_sync(0xffffffffu, v, o);
        if (threadIdx.x == 0)
            out[0] = v / ((float)N_COLS * (float)B);
    }
}

extern "C" void kernel_launch(void* const* d_in, const int* in_sizes, int n_in,
                              void* d_out, int out_size)
{
    const float4* pred = (const float4*)d_in[0];
    const float4* tru  = (const float4*)d_in[1];
    float* out = (float*)d_out;

    const int B = in_sizes[0] / N_COLS;  // 4096

    w1_row_kernel<<<B, NT>>>(pred, tru);
    w1_reduce_kernel<<<1, 1024>>>(out, B);
}

// round 14
// speedup vs baseline: 1.8373x; 1.1193x over previous
#include <cuda_runtime.h>
#include <cuda_bf16.h>

#define N_COLS 4096
#define NT     512
#define M_BKT  2048
#define BPT    (M_BKT / NT)        // 4 buckets owned per thread
#define BKT_W  (1.0f / (float)M_BKT)

__device__ float g_row_sums[8192];

static __device__ __forceinline__ int bkt(float x) {
    int b = (int)(x * (float)M_BKT);
    return (b > M_BKT - 1) ? (M_BKT - 1) : ((b < 0) ? 0 : b);
}

__global__ __launch_bounds__(NT, 3)
void w1_row_kernel(const float4* __restrict__ pred,
                   const float4* __restrict__ tru)
{
    // counts (packed u|v<<16) -> combined offsets -> scatter cursors
    __shared__ unsigned int cursor[M_BKT];          // 8 KB
    __shared__ unsigned int slab[2 * N_COLS];       // 32 KB: bucketed keys
    __shared__ unsigned int wsum[16];
    __shared__ float red[16];

    const int row  = blockIdx.x;
    const int t    = threadIdx.x;
    const int lane = t & 31;
    const int wid  = t >> 5;

    // zero own counters
    #pragma unroll
    for (int j = 0; j < BPT; j++) cursor[t * BPT + j] = 0u;

    const size_t rbase = (size_t)row * (N_COLS / 4);
    float4 p0 = pred[rbase + t];
    float4 p1 = pred[rbase + t + NT];
    float4 q0 = tru[rbase + t];
    float4 q1 = tru[rbase + t + NT];
    __syncthreads();   // counters zeroed before atomics

    // ---- histogram: u -> +1 (low half), v -> +1<<16 (high half) ----
    {
        float up[8] = {p0.x, p0.y, p0.z, p0.w, p1.x, p1.y, p1.z, p1.w};
        float vp[8] = {q0.x, q0.y, q0.z, q0.w, q1.x, q1.y, q1.z, q1.w};
        #pragma unroll
        for (int e = 0; e < 8; e++) atomicAdd(&cursor[bkt(up[e])], 1u);
        #pragma unroll
        for (int e = 0; e < 8; e++) atomicAdd(&cursor[bkt(vp[e])], 0x10000u);
    }
    __syncthreads();

    // ---- packed exclusive scan over M_BKT buckets (thread owns BPT contiguous) ----
    unsigned int eP[BPT];     // packed exclusive prefix within thread
    unsigned int oB[BPT];     // combined slab offset per owned bucket
    int          c0[BPT];     // cumU - cumV entering the bucket
    {
        unsigned int run = 0;
        unsigned int h[BPT];
        #pragma unroll
        for (int j = 0; j < BPT; j++) {
            h[j]  = cursor[t * BPT + j];
            eP[j] = run;
            run  += h[j];
        }
        // warp inclusive scan of run
        unsigned int inc = run;
        #pragma unroll
        for (int o = 1; o < 32; o <<= 1) {
            unsigned int n2 = __shfl_up_sync(0xffffffffu, inc, o);
            if (lane >= o) inc += n2;
        }
        unsigned int wexc = inc - run;
        if (lane == 31) wsum[wid] = inc;
        __syncthreads();
        if (t < 32) {
            unsigned int v2 = (t < 16) ? wsum[t] : 0u;
            unsigned int i2 = v2;
            #pragma unroll
            for (int o = 1; o < 32; o <<= 1) {
                unsigned int n2 = __shfl_up_sync(0xffffffffu, i2, o);
                if (t >= o) i2 += n2;
            }
            if (t < 16) wsum[t] = i2 - v2;   // exclusive warp base
        }
        __syncthreads();
        const unsigned int base = wsum[wid] + wexc;
        #pragma unroll
        for (int j = 0; j < BPT; j++) {
            unsigned int P = base + eP[j];               // packed cumU | cumV<<16
            unsigned int cu = P & 0xFFFFu, cv = P >> 16;
            oB[j] = cu + cv;
            c0[j] = (int)cu - (int)cv;
            cursor[t * BPT + j] = oB[j];                 // own bucket: safe rewrite
        }
    }
    __syncthreads();

    // ---- scatter keys: key = (bits & ~1) | tag  (tag: u=0, v=1) ----
    {
        float up[8] = {p0.x, p0.y, p0.z, p0.w, p1.x, p1.y, p1.z, p1.w};
        float vp[8] = {q0.x, q0.y, q0.z, q0.w, q1.x, q1.y, q1.z, q1.w};
        #pragma unroll
        for (int e = 0; e < 8; e++) {
            unsigned int pos = atomicAdd(&cursor[bkt(up[e])], 1u);
            slab[pos] = __float_as_uint(up[e]) & ~1u;
        }
        #pragma unroll
        for (int e = 0; e < 8; e++) {
            unsigned int pos = atomicAdd(&cursor[bkt(vp[e])], 1u);
            slab[pos] = (__float_as_uint(vp[e]) & ~1u) | 1u;
        }
    }
    __syncthreads();

    // ---- per-bucket integration of |cumU - cumV| ----
    float acc = 0.0f;
    #pragma unroll
    for (int j = 0; j < BPT; j++) {
        const int m   = t * BPT + j;
        const unsigned int o = oB[j];
        const int cnt = (int)(cursor[m] - o);
        const float L = (float)m * BKT_W;
        const float R = L + BKT_W;
        const int ac0 = (c0[j] < 0) ? -c0[j] : c0[j];

        if (ac0 >= cnt) {
            // Sign-constant fast path: integral = |c0*W + sum s_i*(R - x_i)|,
            // order-free — no sort, no walk.
            float s = (float)c0[j] * BKT_W;
            for (int i2 = 0; i2 < cnt; i2++) {
                unsigned int k2 = slab[o + i2];
                float x = __uint_as_float(k2 & ~1u);
                float w = R - x;
                s += (k2 & 1u) ? -w : w;
            }
            acc += fabsf(s);
        } else {
            // Slow path: sort the bucket and walk the counter.
            for (int i2 = 1; i2 < cnt; i2++) {
                unsigned int key = slab[o + i2];
                int j2 = i2 - 1;
                while (j2 >= 0 && slab[o + j2] > key) {
                    slab[o + j2 + 1] = slab[o + j2];
                    j2--;
                }
                slab[o + j2 + 1] = key;
            }
            float xp = L;
            int   c  = c0[j];
            for (int s2 = 0; s2 < cnt; s2++) {
                unsigned int k2 = slab[o + s2];
                float x = __uint_as_float(k2 & ~1u);
                acc += fabsf((float)c) * (x - xp);
                c += (k2 & 1u) ? -1 : 1;
                xp = x;
            }
            acc += fabsf((float)c) * (R - xp);
        }
    }

    // ---- block reduction -> g_row_sums[row] ----
    #pragma unroll
    for (int o = 16; o > 0; o >>= 1)
        acc += __shfl_down_sync(0xffffffffu, acc, o);
    if (lane == 0) red[wid] = acc;
    __syncthreads();
    if (t < 32) {
        float v = (t < 16) ? red[t] : 0.0f;
        #pragma unroll
        for (int o = 8; o > 0; o >>= 1)
            v += __shfl_down_sync(0xffffffffu, v, o);
        if (t == 0) g_row_sums[row] = v;
    }
}

// Deterministic final reduction: single block, fixed iteration order.
__global__ void w1_reduce_kernel(float* __restrict__ out, int B)
{
    __shared__ float red[32];
    float local = 0.0f;
    for (int i = threadIdx.x; i < B; i += 1024)
        local += g_row_sums[i];
    #pragma unroll
    for (int o = 16; o > 0; o >>= 1)
        local += __shfl_down_sync(0xffffffffu, local, o);
    if ((threadIdx.x & 31) == 0) red[threadIdx.x >> 5] = local;
    __syncthreads();
    if (threadIdx.x < 32) {
        float v = red[threadIdx.x];
        #pragma unroll
        for (int o = 16; o > 0; o >>= 1)
            v += __shfl_down_sync(0xffffffffu, v, o);
        if (threadIdx.x == 0)
            out[0] = v / ((float)N_COLS * (float)B);
    }
}

extern "C" void kernel_launch(void* const* d_in, const int* in_sizes, int n_in,
                              void* d_out, int out_size)
{
    const float4* pred = (const float4*)d_in[0];
    const float4* tru  = (const float4*)d_in[1];
    float* out = (float*)d_out;

    const int B = in_sizes[0] / N_COLS;  // 4096

    w1_row_kernel<<<B, NT>>>(pred, tru);
    w1_reduce_kernel<<<1, 1024>>>(out, B);
}